// round 1
// baseline (speedup 1.0000x reference)
#include <cuda_runtime.h>

#define NN 100000
#define EE 1600000
#define FIN 100
#define D 64
#define GG 500

// ---------------- scratch (device globals; no allocs allowed) ----------------
__device__ float g_deg[NN];
__device__ float g_norm[EE];
__device__ float g_out0[NN * D];
__device__ float g_h[NN * D];
__device__ float g_aggA[NN * D];
__device__ float g_aggB[NN * D];
__device__ float g_sums[GG * D];
__device__ float g_cnt[GG];
__device__ int g_is64_edge;
__device__ int g_is64_batch;

__device__ __forceinline__ int load_idx(const void* p, long long i, int is64) {
    return is64 ? (int)((const long long*)p)[i] : ((const int*)p)[i];
}

// Detect whether index arrays are int64 (odd 32-bit words all zero) or int32.
// Samples are strided (always-odd word indices) so a sorted int32 batch array
// (leading zeros) can't fool the check.
__global__ void detect_kernel(const int* ei, const int* bat) {
    int i = threadIdx.x;  // 32 threads
    int nz_e = 0, nz_b = 0;
    for (int j = i; j < 128; j += 32) {
        int w = 1 + 700 * j;  // always odd, max 88901 < 100000 words
        nz_e |= (ei[w] != 0);
        nz_b |= (bat[w] != 0);
    }
    unsigned be = __ballot_sync(0xffffffffu, nz_e);
    unsigned bb = __ballot_sync(0xffffffffu, nz_b);
    if (i == 0) {
        g_is64_edge = (be == 0);
        g_is64_batch = (bb == 0);
    }
}

// ---------------- degree + symmetric norm ----------------
__global__ void deg_kernel(const void* ei, const float* __restrict__ w) {
    int e = blockIdx.x * blockDim.x + threadIdx.x;
    if (e >= EE) return;
    int c = load_idx(ei, (long long)EE + e, g_is64_edge);
    atomicAdd(&g_deg[c], w[e]);
}

__global__ void norm_kernel(const void* ei, const float* __restrict__ w) {
    int e = blockIdx.x * blockDim.x + threadIdx.x;
    if (e >= EE) return;
    int is64 = g_is64_edge;
    int r = load_idx(ei, e, is64);
    int c = load_idx(ei, (long long)EE + e, is64);
    float dr = g_deg[r], dc = g_deg[c];
    float ir = dr > 0.f ? rsqrtf(dr) : 0.f;
    float ic = dc > 0.f ? rsqrtf(dc) : 0.f;
    g_norm[e] = ir * w[e] * ic;
}

// ---------------- dense GEMM: C[nrows,64] = A'[nrows,K] @ W[K,64] ----------------
// A' = relu(A + biasA) if biasA != null (per-K bias), else A.
// C  = relu(C + biasC) if biasC != null.
// Block: 64 rows x 64 cols, 256 threads (16x16), 4x4 per thread.
template <int K, int KB>
__global__ void gemm64(const float* __restrict__ A, const float* __restrict__ W,
                       const float* __restrict__ biasA, const float* __restrict__ biasC,
                       float* __restrict__ C, int nrows) {
    __shared__ float Ws[K * D];
    __shared__ float As[KB * 65];  // transposed [k][row], pad 65 to avoid conflicts

    int tid = threadIdx.x;
    int row0 = blockIdx.x * 64;
    for (int i = tid; i < K * D; i += 256) Ws[i] = W[i];

    int tx = tid & 15, ty = tid >> 4;
    float acc[4][4] = {};

    for (int kb = 0; kb < K; kb += KB) {
        __syncthreads();  // (also guards Ws on first iteration)
        for (int i = tid; i < 64 * KB; i += 256) {
            int rr = i / KB, kk = i - rr * KB;
            int r = row0 + rr;
            float v = 0.f;
            if (r < nrows) {
                v = A[(long long)r * K + kb + kk];
                if (biasA) v = fmaxf(v + biasA[kb + kk], 0.f);
            }
            As[kk * 65 + rr] = v;
        }
        __syncthreads();
#pragma unroll
        for (int k = 0; k < KB; k++) {
            float a0 = As[k * 65 + ty * 4 + 0];
            float a1 = As[k * 65 + ty * 4 + 1];
            float a2 = As[k * 65 + ty * 4 + 2];
            float a3 = As[k * 65 + ty * 4 + 3];
            float4 wv = *(const float4*)&Ws[(kb + k) * D + tx * 4];
            acc[0][0] += a0 * wv.x; acc[0][1] += a0 * wv.y; acc[0][2] += a0 * wv.z; acc[0][3] += a0 * wv.w;
            acc[1][0] += a1 * wv.x; acc[1][1] += a1 * wv.y; acc[1][2] += a1 * wv.z; acc[1][3] += a1 * wv.w;
            acc[2][0] += a2 * wv.x; acc[2][1] += a2 * wv.y; acc[2][2] += a2 * wv.z; acc[2][3] += a2 * wv.w;
            acc[3][0] += a3 * wv.x; acc[3][1] += a3 * wv.y; acc[3][2] += a3 * wv.z; acc[3][3] += a3 * wv.w;
        }
    }

    int c0 = tx * 4;
    float4 bc = make_float4(0.f, 0.f, 0.f, 0.f);
    if (biasC) bc = *(const float4*)&biasC[c0];
#pragma unroll
    for (int i2 = 0; i2 < 4; i2++) {
        int r = row0 + ty * 4 + i2;
        if (r >= nrows) break;
        float4 v = make_float4(acc[i2][0], acc[i2][1], acc[i2][2], acc[i2][3]);
        if (biasC) {
            v.x = fmaxf(v.x + bc.x, 0.f);
            v.y = fmaxf(v.y + bc.y, 0.f);
            v.z = fmaxf(v.z + bc.z, 0.f);
            v.w = fmaxf(v.w + bc.w, 0.f);
        }
        *(float4*)&C[(long long)r * D + c0] = v;
    }
}

// ---------------- edge scatter: agg[col] += h[row] * norm ----------------
// 4 threads per edge, each handles 16 floats via 4x (LDG.128 + red.v4.f32).
__device__ __forceinline__ void red_add_v4(float4* addr, float4 v) {
    asm volatile("red.global.add.v4.f32 [%0], {%1,%2,%3,%4};"
                 :: "l"(addr), "f"(v.x), "f"(v.y), "f"(v.z), "f"(v.w)
                 : "memory");
}

__global__ void edge_kernel(const void* ei, const float* __restrict__ h,
                            float* __restrict__ agg) {
    int t = blockIdx.x * blockDim.x + threadIdx.x;
    int e = t >> 2;
    if (e >= EE) return;
    int q = t & 3;
    int is64 = g_is64_edge;
    int r = load_idx(ei, e, is64);
    int c = load_idx(ei, (long long)EE + e, is64);
    float nv = g_norm[e];
    const float4* hp = (const float4*)(h + (long long)r * D) + q * 4;
    float4* ap = (float4*)(agg + (long long)c * D) + q * 4;
#pragma unroll
    for (int i = 0; i < 4; i++) {
        float4 v = hp[i];
        v.x *= nv; v.y *= nv; v.z *= nv; v.w *= nv;
        red_add_v4(ap + i, v);
    }
}

// ---------------- mean pool: sums[batch[n]] += relu(agg[n]+bias), cnt++ ----------------
__global__ void pool_kernel(const void* batch, const float* __restrict__ agg,
                            const float* __restrict__ bias) {
    int t = blockIdx.x * blockDim.x + threadIdx.x;
    int n = t >> 4;
    if (n >= NN) return;
    int q = t & 15;
    int g = load_idx(batch, n, g_is64_batch);
    float4 v = *((const float4*)(agg + (long long)n * D) + q);
    float4 b = ((const float4*)bias)[q];
    v.x = fmaxf(v.x + b.x, 0.f);
    v.y = fmaxf(v.y + b.y, 0.f);
    v.z = fmaxf(v.z + b.z, 0.f);
    v.w = fmaxf(v.w + b.w, 0.f);
    red_add_v4((float4*)(g_sums + g * D) + q, v);
    if (q == 0) atomicAdd(&g_cnt[g], 1.0f);
}

// ---------------- fused MLP tail: lin1 -> fc0 -> fc1 -> lin2 ----------------
__global__ void tail_kernel(const float* __restrict__ W1, const float* __restrict__ b1,
                            const float* __restrict__ fcw, const float* __restrict__ fcb,
                            const float* __restrict__ w2, const float* __restrict__ b2,
                            float* __restrict__ out) {
    int g = blockIdx.x, tid = threadIdx.x;  // 64 threads
    __shared__ float buf[2][64];
    __shared__ float red[64];

    buf[0][tid] = g_sums[g * D + tid] / fmaxf(g_cnt[g], 1.f);
    __syncthreads();

    // lin1 + relu
    {
        float acc = 0.f;
#pragma unroll
        for (int k = 0; k < 64; k++) acc += buf[0][k] * W1[k * D + tid];
        buf[1][tid] = fmaxf(acc + b1[tid], 0.f);
        __syncthreads();
    }
    int cur = 1;
    // 2x fc + relu
    for (int L = 0; L < 2; L++) {
        const float* W = fcw + L * D * D;
        float acc = 0.f;
#pragma unroll
        for (int k = 0; k < 64; k++) acc += buf[cur][k] * W[k * D + tid];
        __syncthreads();
        buf[cur ^ 1][tid] = fmaxf(acc + fcb[L * D + tid], 0.f);
        cur ^= 1;
        __syncthreads();
    }
    // lin2: dot(buf[cur], w2) + b2
    red[tid] = buf[cur][tid] * w2[tid];
    __syncthreads();
    if (tid < 32) {
        float s = red[tid] + red[tid + 32];
#pragma unroll
        for (int off = 16; off; off >>= 1) s += __shfl_down_sync(0xffffffffu, s, off);
        if (tid == 0) out[g] = s + b2[0];
    }
}

// ---------------- launch ----------------
extern "C" void kernel_launch(void* const* d_in, const int* in_sizes, int n_in,
                              void* d_out, int out_size) {
    const float* x      = (const float*)d_in[0];
    const void*  ei     = d_in[1];
    const float* ew     = (const float*)d_in[2];
    const void*  batch  = d_in[3];
    const float* lin0_w = (const float*)d_in[4];
    const float* lin0_b = (const float*)d_in[5];
    const float* conv_w = (const float*)d_in[6];
    const float* conv_b = (const float*)d_in[7];
    const float* lin1_w = (const float*)d_in[8];
    const float* lin1_b = (const float*)d_in[9];
    const float* fc_w   = (const float*)d_in[10];
    const float* fc_b   = (const float*)d_in[11];
    const float* lin2_w = (const float*)d_in[12];
    const float* lin2_b = (const float*)d_in[13];
    float* out = (float*)d_out;

    float *p_out0, *p_h, *p_aggA, *p_aggB, *p_deg, *p_sums, *p_cnt;
    cudaGetSymbolAddress((void**)&p_out0, g_out0);
    cudaGetSymbolAddress((void**)&p_h,    g_h);
    cudaGetSymbolAddress((void**)&p_aggA, g_aggA);
    cudaGetSymbolAddress((void**)&p_aggB, g_aggB);
    cudaGetSymbolAddress((void**)&p_deg,  g_deg);
    cudaGetSymbolAddress((void**)&p_sums, g_sums);
    cudaGetSymbolAddress((void**)&p_cnt,  g_cnt);

    detect_kernel<<<1, 32>>>((const int*)ei, (const int*)batch);

    cudaMemsetAsync(p_deg, 0, NN * sizeof(float));
    deg_kernel<<<(EE + 255) / 256, 256>>>(ei, ew);
    norm_kernel<<<(EE + 255) / 256, 256>>>(ei, ew);

    const int GB = (NN + 63) / 64;
    gemm64<FIN, 25><<<GB, 256>>>(x, lin0_w, nullptr, lin0_b, p_out0, NN);

    float* bufs[2] = {p_aggA, p_aggB};
    const float* Ain = p_out0;
    const float* bA = nullptr;
    for (int i = 0; i < 4; i++) {
        float* agg = bufs[i & 1];
        cudaMemsetAsync(agg, 0, (size_t)NN * D * sizeof(float));
        gemm64<D, 32><<<GB, 256>>>(Ain, conv_w + i * D * D, bA, nullptr, p_h, NN);
        edge_kernel<<<(4 * EE) / 256, 256>>>(ei, p_h, agg);
        Ain = agg;
        bA = conv_b + i * D;
    }

    cudaMemsetAsync(p_sums, 0, GG * D * sizeof(float));
    cudaMemsetAsync(p_cnt, 0, GG * sizeof(float));
    pool_kernel<<<(16 * NN) / 256, 256>>>(batch, Ain, bA);
    tail_kernel<<<GG, 64>>>(lin1_w, lin1_b, fc_w, fc_b, lin2_w, lin2_b, out);
}

// round 3
// speedup vs baseline: 1.7774x; 1.7774x over previous
#include <cuda_runtime.h>

#define NN 100000
#define EE 1600000
#define FIN 100
#define D 64
#define GG 500
#define SCAN_T 512
#define SCAN_NB ((NN + SCAN_T - 1) / SCAN_T)

// ---------------- scratch (device globals; no allocs allowed) ----------------
__device__ float g_deg[NN];
__device__ int   g_cntn[NN];
__device__ int   g_ptr[NN + 1];
__device__ int   g_fill[NN];
__device__ int   g_partials[SCAN_NB];
__device__ int   g_csr_row[EE];
__device__ float g_csr_norm[EE];
__device__ float g_out0[NN * D];
__device__ float g_h[NN * D];
__device__ float g_aggA[NN * D];
__device__ float g_aggB[NN * D];
__device__ float g_sums[GG * D];
__device__ float g_cnt[GG];
__device__ int g_is64_edge;
__device__ int g_is64_batch;

__device__ __forceinline__ int load_idx(const void* p, long long i, int is64) {
    return is64 ? (int)((const long long*)p)[i] : ((const int*)p)[i];
}

// Detect int64 vs int32 index arrays (odd 32-bit words all zero => int64).
__global__ void detect_kernel(const int* ei, const int* bat) {
    int i = threadIdx.x;  // 32 threads
    int nz_e = 0, nz_b = 0;
    for (int j = i; j < 128; j += 32) {
        int w = 1 + 700 * j;  // always odd, < NN words
        nz_e |= (ei[w] != 0);
        nz_b |= (bat[w] != 0);
    }
    unsigned be = __ballot_sync(0xffffffffu, nz_e);
    unsigned bb = __ballot_sync(0xffffffffu, nz_b);
    if (i == 0) {
        g_is64_edge = (be == 0);
        g_is64_batch = (bb == 0);
    }
}

// ---------------- degree (weighted) + count histogram ----------------
__global__ void deg_kernel(const void* ei, const float* __restrict__ w) {
    int e = blockIdx.x * blockDim.x + threadIdx.x;
    if (e >= EE) return;
    int c = load_idx(ei, (long long)EE + e, g_is64_edge);
    atomicAdd(&g_deg[c], w[e]);
    atomicAdd(&g_cntn[c], 1);
}

// ---------------- two-level exclusive scan over g_cntn -> g_ptr ----------------
__global__ void scan1_kernel() {
    __shared__ int sh[SCAN_T];
    int tid = threadIdx.x;
    int i = blockIdx.x * SCAN_T + tid;
    int v = (i < NN) ? g_cntn[i] : 0;
    sh[tid] = v;
    __syncthreads();
    for (int off = 1; off < SCAN_T; off <<= 1) {
        int t = (tid >= off) ? sh[tid - off] : 0;
        __syncthreads();
        sh[tid] += t;
        __syncthreads();
    }
    if (i < NN) g_ptr[i] = sh[tid] - v;  // exclusive
    if (tid == SCAN_T - 1) g_partials[blockIdx.x] = sh[tid];
}

__global__ void scan2_kernel() {  // 1 block of 256 (SCAN_NB=196 < 256)
    __shared__ int sh[256];
    int tid = threadIdx.x;
    int v = (tid < SCAN_NB) ? g_partials[tid] : 0;
    sh[tid] = v;
    __syncthreads();
    for (int off = 1; off < 256; off <<= 1) {
        int t = (tid >= off) ? sh[tid - off] : 0;
        __syncthreads();
        sh[tid] += t;
        __syncthreads();
    }
    if (tid < SCAN_NB) g_partials[tid] = sh[tid] - v;  // exclusive
}

__global__ void scan3_kernel() {
    int i = blockIdx.x * blockDim.x + threadIdx.x;
    if (i < NN) g_ptr[i] += g_partials[i / SCAN_T];
    if (i == 0) g_ptr[NN] = EE;
}

// ---------------- scatter edges into CSR (by destination), norm inline -------
__global__ void scatter_kernel(const void* ei, const float* __restrict__ w) {
    int e = blockIdx.x * blockDim.x + threadIdx.x;
    if (e >= EE) return;
    int is64 = g_is64_edge;
    int r = load_idx(ei, e, is64);
    int c = load_idx(ei, (long long)EE + e, is64);
    float dr = g_deg[r], dc = g_deg[c];
    float ir = dr > 0.f ? rsqrtf(dr) : 0.f;
    float ic = dc > 0.f ? rsqrtf(dc) : 0.f;
    int p = g_ptr[c] + atomicAdd(&g_fill[c], 1);
    g_csr_row[p] = r;
    g_csr_norm[p] = ir * w[e] * ic;
}

// ---------------- dense GEMM: C[nrows,64] = A[nrows,K] @ W[K,64] -------------
// 128-row x 64-col tile, 256 threads, 8x4 per thread, transposed-As float4 loads.
// C = relu(C + biasC) if biasC != null, else plain.
#define APAD 132  // 128 + 4, multiple of 4 for LDS.128 alignment
template <int K, int KB>
__global__ void gemm64(const float* __restrict__ A, const float* __restrict__ W,
                       const float* __restrict__ biasC,
                       float* __restrict__ C, int nrows) {
    __shared__ float Ws[K * D];
    __shared__ float As[KB * APAD];  // [k][row]

    int tid = threadIdx.x;
    int row0 = blockIdx.x * 128;
    for (int i = tid; i < K * D; i += 256) Ws[i] = W[i];

    int tx = tid & 15, ty = tid >> 4;  // tx: 4 cols, ty: 8 rows
    float acc[8][4] = {};

    for (int kb = 0; kb < K; kb += KB) {
        __syncthreads();  // also guards Ws on first iteration
        for (int i = tid; i < 128 * KB; i += 256) {
            int rr = i / KB, kk = i - rr * KB;
            int r = row0 + rr;
            float v = (r < nrows) ? A[(long long)r * K + kb + kk] : 0.f;
            As[kk * APAD + rr] = v;
        }
        __syncthreads();
#pragma unroll
        for (int k = 0; k < KB; k++) {
            float4 a0 = *(const float4*)&As[k * APAD + ty * 8];
            float4 a1 = *(const float4*)&As[k * APAD + ty * 8 + 4];
            float4 wv = *(const float4*)&Ws[(kb + k) * D + tx * 4];
            float av[8] = {a0.x, a0.y, a0.z, a0.w, a1.x, a1.y, a1.z, a1.w};
#pragma unroll
            for (int i2 = 0; i2 < 8; i2++) {
                acc[i2][0] += av[i2] * wv.x;
                acc[i2][1] += av[i2] * wv.y;
                acc[i2][2] += av[i2] * wv.z;
                acc[i2][3] += av[i2] * wv.w;
            }
        }
    }

    int c0 = tx * 4;
    float4 bc = make_float4(0.f, 0.f, 0.f, 0.f);
    if (biasC) bc = *(const float4*)&biasC[c0];
#pragma unroll
    for (int i2 = 0; i2 < 8; i2++) {
        int r = row0 + ty * 8 + i2;
        if (r >= nrows) break;
        float4 v = make_float4(acc[i2][0], acc[i2][1], acc[i2][2], acc[i2][3]);
        if (biasC) {
            v.x = fmaxf(v.x + bc.x, 0.f);
            v.y = fmaxf(v.y + bc.y, 0.f);
            v.z = fmaxf(v.z + bc.z, 0.f);
            v.w = fmaxf(v.w + bc.w, 0.f);
        }
        *(float4*)&C[(long long)r * D + c0] = v;
    }
}

// ---------------- CSR aggregation: out[n] = relu(sum_e h[row_e]*norm_e + b) --
// One warp per node; 2 edges in flight (q=0/1), 16 lanes x float4 cover 64 cols.
__global__ void agg_csr(const float* __restrict__ h,
                        const int* __restrict__ rows, const float* __restrict__ norms,
                        const float* __restrict__ bias, float* __restrict__ outp) {
    int warp = (blockIdx.x * blockDim.x + threadIdx.x) >> 5;
    if (warp >= NN) return;
    int lane = threadIdx.x & 31;
    int q = lane >> 4, p = lane & 15;
    int s = g_ptr[warp], e = g_ptr[warp + 1];
    float4 acc = make_float4(0.f, 0.f, 0.f, 0.f);
    for (int i = s + q; i < e; i += 2) {
        int r = rows[i];
        float nv = norms[i];
        float4 v = *((const float4*)(h + (long long)r * D) + p);
        acc.x += v.x * nv; acc.y += v.y * nv; acc.z += v.z * nv; acc.w += v.w * nv;
    }
    acc.x += __shfl_xor_sync(0xffffffffu, acc.x, 16);
    acc.y += __shfl_xor_sync(0xffffffffu, acc.y, 16);
    acc.z += __shfl_xor_sync(0xffffffffu, acc.z, 16);
    acc.w += __shfl_xor_sync(0xffffffffu, acc.w, 16);
    if (q == 0) {
        float4 b = ((const float4*)bias)[p];
        acc.x = fmaxf(acc.x + b.x, 0.f);
        acc.y = fmaxf(acc.y + b.y, 0.f);
        acc.z = fmaxf(acc.z + b.z, 0.f);
        acc.w = fmaxf(acc.w + b.w, 0.f);
        *((float4*)(outp + (long long)warp * D) + p) = acc;
    }
}

// ---------------- mean pool: sums[batch[n]] += out[n], cnt++ -----------------
__device__ __forceinline__ void red_add_v4(float4* addr, float4 v) {
    asm volatile("red.global.add.v4.f32 [%0], {%1,%2,%3,%4};"
                 :: "l"(addr), "f"(v.x), "f"(v.y), "f"(v.z), "f"(v.w)
                 : "memory");
}

__global__ void pool_kernel(const void* batch, const float* __restrict__ src) {
    int t = blockIdx.x * blockDim.x + threadIdx.x;
    int n = t >> 4;
    if (n >= NN) return;
    int q = t & 15;
    int g = load_idx(batch, n, g_is64_batch);
    float4 v = *((const float4*)(src + (long long)n * D) + q);
    red_add_v4((float4*)(g_sums + g * D) + q, v);
    if (q == 0) atomicAdd(&g_cnt[g], 1.0f);
}

// ---------------- fused MLP tail: lin1 -> fc0 -> fc1 -> lin2 ----------------
__global__ void tail_kernel(const float* __restrict__ W1, const float* __restrict__ b1,
                            const float* __restrict__ fcw, const float* __restrict__ fcb,
                            const float* __restrict__ w2, const float* __restrict__ b2,
                            float* __restrict__ out) {
    int g = blockIdx.x, tid = threadIdx.x;  // 64 threads
    __shared__ float buf[2][64];
    __shared__ float red[64];

    buf[0][tid] = g_sums[g * D + tid] / fmaxf(g_cnt[g], 1.f);
    __syncthreads();
    {
        float acc = 0.f;
#pragma unroll
        for (int k = 0; k < 64; k++) acc += buf[0][k] * W1[k * D + tid];
        buf[1][tid] = fmaxf(acc + b1[tid], 0.f);
        __syncthreads();
    }
    int cur = 1;
    for (int L = 0; L < 2; L++) {
        const float* W = fcw + L * D * D;
        float acc = 0.f;
#pragma unroll
        for (int k = 0; k < 64; k++) acc += buf[cur][k] * W[k * D + tid];
        __syncthreads();
        buf[cur ^ 1][tid] = fmaxf(acc + fcb[L * D + tid], 0.f);
        cur ^= 1;
        __syncthreads();
    }
    red[tid] = buf[cur][tid] * w2[tid];
    __syncthreads();
    if (tid < 32) {
        float s = red[tid] + red[tid + 32];
#pragma unroll
        for (int off = 16; off; off >>= 1) s += __shfl_down_sync(0xffffffffu, s, off);
        if (tid == 0) out[g] = s + b2[0];
    }
}

// ---------------- launch ----------------
extern "C" void kernel_launch(void* const* d_in, const int* in_sizes, int n_in,
                              void* d_out, int out_size) {
    const float* x      = (const float*)d_in[0];
    const void*  ei     = d_in[1];
    const float* ew     = (const float*)d_in[2];
    const void*  batch  = d_in[3];
    const float* lin0_w = (const float*)d_in[4];
    const float* lin0_b = (const float*)d_in[5];
    const float* conv_w = (const float*)d_in[6];
    const float* conv_b = (const float*)d_in[7];
    const float* lin1_w = (const float*)d_in[8];
    const float* lin1_b = (const float*)d_in[9];
    const float* fc_w   = (const float*)d_in[10];
    const float* fc_b   = (const float*)d_in[11];
    const float* lin2_w = (const float*)d_in[12];
    const float* lin2_b = (const float*)d_in[13];
    float* out = (float*)d_out;

    float *p_out0, *p_h, *p_aggA, *p_aggB, *p_deg, *p_sums, *p_cnt, *p_norms;
    int *p_cntn, *p_fill, *p_rows;
    cudaGetSymbolAddress((void**)&p_out0, g_out0);
    cudaGetSymbolAddress((void**)&p_h,    g_h);
    cudaGetSymbolAddress((void**)&p_aggA, g_aggA);
    cudaGetSymbolAddress((void**)&p_aggB, g_aggB);
    cudaGetSymbolAddress((void**)&p_deg,  g_deg);
    cudaGetSymbolAddress((void**)&p_sums, g_sums);
    cudaGetSymbolAddress((void**)&p_cnt,  g_cnt);
    cudaGetSymbolAddress((void**)&p_cntn, g_cntn);
    cudaGetSymbolAddress((void**)&p_fill, g_fill);
    cudaGetSymbolAddress((void**)&p_rows, g_csr_row);
    cudaGetSymbolAddress((void**)&p_norms, g_csr_norm);

    detect_kernel<<<1, 32>>>((const int*)ei, (const int*)batch);

    cudaMemsetAsync(p_deg, 0, NN * sizeof(float));
    cudaMemsetAsync(p_cntn, 0, NN * sizeof(int));
    cudaMemsetAsync(p_fill, 0, NN * sizeof(int));

    deg_kernel<<<(EE + 255) / 256, 256>>>(ei, ew);
    scan1_kernel<<<SCAN_NB, SCAN_T>>>();
    scan2_kernel<<<1, 256>>>();
    scan3_kernel<<<(NN + 255) / 256, 256>>>();
    scatter_kernel<<<(EE + 255) / 256, 256>>>(ei, ew);

    const int GB = (NN + 127) / 128;
    gemm64<FIN, 20><<<GB, 256>>>(x, lin0_w, lin0_b, p_out0, NN);

    float* bufs[2] = {p_aggA, p_aggB};
    const float* Ain = p_out0;
    for (int i = 0; i < 4; i++) {
        float* agg = bufs[i & 1];
        gemm64<D, 32><<<GB, 256>>>(Ain, conv_w + i * D * D, nullptr, p_h, NN);
        agg_csr<<<(NN * 32 + 255) / 256, 256>>>(p_h, p_rows, p_norms, conv_b + i * D, agg);
        Ain = agg;
    }

    cudaMemsetAsync(p_sums, 0, GG * D * sizeof(float));
    cudaMemsetAsync(p_cnt, 0, GG * sizeof(float));
    pool_kernel<<<(16 * NN + 255) / 256, 256>>>(batch, Ain);
    tail_kernel<<<GG, 64>>>(lin1_w, lin1_b, fc_w, fc_b, lin2_w, lin2_b, out);
}

// round 4
// speedup vs baseline: 1.7791x; 1.0010x over previous
#include <cuda_runtime.h>
#include <cuda_fp16.h>

#define NN 100000
#define EE 1600000
#define FIN 100
#define D 64
#define GG 500
#define SCAN_T 512
#define SCAN_NB ((NN + SCAN_T - 1) / SCAN_T)

// ---------------- scratch (device globals; no allocs allowed) ----------------
__device__ float g_deg[NN];
__device__ int   g_cntn[NN];
__device__ int   g_ptr[NN + 1];
__device__ int   g_fill[NN];
__device__ int   g_partials[SCAN_NB];
__device__ int   g_csr_row[EE];
__device__ float g_csr_norm[EE];
__device__ float g_out0[NN * D];
__device__ uint4 g_hh[NN * 8];     // h in fp16: 64 halves = 8 uint4 per row
__device__ float g_aggA[NN * D];
__device__ float g_aggB[NN * D];
__device__ float g_sums[GG * D];
__device__ float g_cnt[GG];
__device__ int g_is64_edge;
__device__ int g_is64_batch;

__device__ __forceinline__ int load_idx(const void* p, long long i, int is64) {
    return is64 ? (int)((const long long*)p)[i] : ((const int*)p)[i];
}

// Detect int64 vs int32 index arrays (odd 32-bit words all zero => int64).
__global__ void detect_kernel(const int* ei, const int* bat) {
    int i = threadIdx.x;  // 32 threads
    int nz_e = 0, nz_b = 0;
    for (int j = i; j < 128; j += 32) {
        int w = 1 + 700 * j;  // always odd, < NN words
        nz_e |= (ei[w] != 0);
        nz_b |= (bat[w] != 0);
    }
    unsigned be = __ballot_sync(0xffffffffu, nz_e);
    unsigned bb = __ballot_sync(0xffffffffu, nz_b);
    if (i == 0) {
        g_is64_edge = (be == 0);
        g_is64_batch = (bb == 0);
    }
}

// ---------------- degree (weighted) + count histogram ----------------
__global__ void deg_kernel(const void* ei, const float* __restrict__ w) {
    int e = blockIdx.x * blockDim.x + threadIdx.x;
    if (e >= EE) return;
    int c = load_idx(ei, (long long)EE + e, g_is64_edge);
    atomicAdd(&g_deg[c], w[e]);
    atomicAdd(&g_cntn[c], 1);
}

// ---------------- two-level exclusive scan over g_cntn -> g_ptr ----------------
__global__ void scan1_kernel() {
    __shared__ int sh[SCAN_T];
    int tid = threadIdx.x;
    int i = blockIdx.x * SCAN_T + tid;
    int v = (i < NN) ? g_cntn[i] : 0;
    sh[tid] = v;
    __syncthreads();
    for (int off = 1; off < SCAN_T; off <<= 1) {
        int t = (tid >= off) ? sh[tid - off] : 0;
        __syncthreads();
        sh[tid] += t;
        __syncthreads();
    }
    if (i < NN) g_ptr[i] = sh[tid] - v;  // exclusive
    if (tid == SCAN_T - 1) g_partials[blockIdx.x] = sh[tid];
}

__global__ void scan2_kernel() {  // 1 block of 256 (SCAN_NB=196 < 256)
    __shared__ int sh[256];
    int tid = threadIdx.x;
    int v = (tid < SCAN_NB) ? g_partials[tid] : 0;
    sh[tid] = v;
    __syncthreads();
    for (int off = 1; off < 256; off <<= 1) {
        int t = (tid >= off) ? sh[tid - off] : 0;
        __syncthreads();
        sh[tid] += t;
        __syncthreads();
    }
    if (tid < SCAN_NB) g_partials[tid] = sh[tid] - v;  // exclusive
}

__global__ void scan3_kernel() {
    int i = blockIdx.x * blockDim.x + threadIdx.x;
    if (i < NN) g_ptr[i] += g_partials[i / SCAN_T];
    if (i == 0) g_ptr[NN] = EE;
}

// ---------------- scatter edges into CSR (by destination), norm inline -------
__global__ void scatter_kernel(const void* ei, const float* __restrict__ w) {
    int e = blockIdx.x * blockDim.x + threadIdx.x;
    if (e >= EE) return;
    int is64 = g_is64_edge;
    int r = load_idx(ei, e, is64);
    int c = load_idx(ei, (long long)EE + e, is64);
    float dr = g_deg[r], dc = g_deg[c];
    float ir = dr > 0.f ? rsqrtf(dr) : 0.f;
    float ic = dc > 0.f ? rsqrtf(dc) : 0.f;
    int p = g_ptr[c] + atomicAdd(&g_fill[c], 1);
    g_csr_row[p] = r;
    g_csr_norm[p] = ir * w[e] * ic;
}

// ---------------- dense GEMM: C[nrows,64] = A[nrows,K] @ W[K,64] -------------
// 128-row x 64-col tile, 256 threads, 8x4 per thread.
// If biasC != null: C = relu(C + biasC). HALF_OUT: store fp16 rows (uint2/thread).
#define APAD 132  // 128 + 4
template <int K, int KB, bool HALF_OUT>
__global__ void gemm64(const float* __restrict__ A, const float* __restrict__ W,
                       const float* __restrict__ biasC,
                       void* __restrict__ Cout, int nrows) {
    __shared__ float Ws[K * D];
    __shared__ float As[KB * APAD];  // [k][row]

    int tid = threadIdx.x;
    int row0 = blockIdx.x * 128;
    for (int i = tid; i < K * D; i += 256) Ws[i] = W[i];

    int tx = tid & 15, ty = tid >> 4;  // tx: 4 cols, ty: 8 rows
    float acc[8][4] = {};

    for (int kb = 0; kb < K; kb += KB) {
        __syncthreads();  // also guards Ws on first iteration
        for (int i = tid; i < 128 * KB; i += 256) {
            int rr = i / KB, kk = i - rr * KB;
            int r = row0 + rr;
            float v = (r < nrows) ? A[(long long)r * K + kb + kk] : 0.f;
            As[kk * APAD + rr] = v;
        }
        __syncthreads();
#pragma unroll
        for (int k = 0; k < KB; k++) {
            float4 a0 = *(const float4*)&As[k * APAD + ty * 8];
            float4 a1 = *(const float4*)&As[k * APAD + ty * 8 + 4];
            float4 wv = *(const float4*)&Ws[(kb + k) * D + tx * 4];
            float av[8] = {a0.x, a0.y, a0.z, a0.w, a1.x, a1.y, a1.z, a1.w};
#pragma unroll
            for (int i2 = 0; i2 < 8; i2++) {
                acc[i2][0] += av[i2] * wv.x;
                acc[i2][1] += av[i2] * wv.y;
                acc[i2][2] += av[i2] * wv.z;
                acc[i2][3] += av[i2] * wv.w;
            }
        }
    }

    int c0 = tx * 4;
    float4 bc = make_float4(0.f, 0.f, 0.f, 0.f);
    if (biasC) bc = *(const float4*)&biasC[c0];
#pragma unroll
    for (int i2 = 0; i2 < 8; i2++) {
        int r = row0 + ty * 8 + i2;
        if (r >= nrows) break;
        float4 v = make_float4(acc[i2][0], acc[i2][1], acc[i2][2], acc[i2][3]);
        if (biasC) {
            v.x = fmaxf(v.x + bc.x, 0.f);
            v.y = fmaxf(v.y + bc.y, 0.f);
            v.z = fmaxf(v.z + bc.z, 0.f);
            v.w = fmaxf(v.w + bc.w, 0.f);
        }
        if (HALF_OUT) {
            __half2 ha = __floats2half2_rn(v.x, v.y);
            __half2 hb = __floats2half2_rn(v.z, v.w);
            uint2 u;
            u.x = *(unsigned*)&ha;
            u.y = *(unsigned*)&hb;
            ((uint2*)Cout)[(long long)r * 16 + tx] = u;
        } else {
            *(float4*)&((float*)Cout)[(long long)r * D + c0] = v;
        }
    }
}

// ---------------- CSR aggregation (fp16 gather) ------------------------------
// One warp per node; 4 edges in flight (q=lane>>3), 8 lanes x uint4 = 128B row.
__device__ __forceinline__ void agg_core(int node, const uint4* __restrict__ h,
                                         const int* __restrict__ rows,
                                         const float* __restrict__ norms,
                                         int q, int p, float acc[8]) {
    int s = g_ptr[node], e = g_ptr[node + 1];
    for (int i = s + q; i < e; i += 4) {
        int r = rows[i];
        float nv = norms[i];
        uint4 u = h[r * 8 + p];
        __half2* hh = (__half2*)&u;
#pragma unroll
        for (int c = 0; c < 4; c++) {
            float2 f = __half22float2(hh[c]);
            acc[2 * c]     += f.x * nv;
            acc[2 * c + 1] += f.y * nv;
        }
    }
#pragma unroll
    for (int c = 0; c < 8; c++) {
        acc[c] += __shfl_xor_sync(0xffffffffu, acc[c], 8);
        acc[c] += __shfl_xor_sync(0xffffffffu, acc[c], 16);
    }
}

__global__ void agg_half(const uint4* __restrict__ h,
                         const int* __restrict__ rows, const float* __restrict__ norms,
                         const float* __restrict__ bias, float* __restrict__ outp) {
    int node = (blockIdx.x * blockDim.x + threadIdx.x) >> 5;
    if (node >= NN) return;
    int lane = threadIdx.x & 31;
    int q = lane >> 3, p = lane & 7;
    float acc[8] = {};
    agg_core(node, h, rows, norms, q, p, acc);
    if (q == 0) {
        float4 b0 = *(const float4*)&bias[8 * p];
        float4 b1 = *(const float4*)&bias[8 * p + 4];
        float4 o0 = make_float4(fmaxf(acc[0] + b0.x, 0.f), fmaxf(acc[1] + b0.y, 0.f),
                                fmaxf(acc[2] + b0.z, 0.f), fmaxf(acc[3] + b0.w, 0.f));
        float4 o1 = make_float4(fmaxf(acc[4] + b1.x, 0.f), fmaxf(acc[5] + b1.y, 0.f),
                                fmaxf(acc[6] + b1.z, 0.f), fmaxf(acc[7] + b1.w, 0.f));
        float* row = outp + (long long)node * D + 8 * p;
        *(float4*)row = o0;
        *(float4*)(row + 4) = o1;
    }
}

__device__ __forceinline__ void red_add_v4(float4* addr, float4 v) {
    asm volatile("red.global.add.v4.f32 [%0], {%1,%2,%3,%4};"
                 :: "l"(addr), "f"(v.x), "f"(v.y), "f"(v.z), "f"(v.w)
                 : "memory");
}

// Last layer: aggregate + bias + relu + mean-pool accumulate (skips out4 buffer).
__global__ void agg_pool(const uint4* __restrict__ h,
                         const int* __restrict__ rows, const float* __restrict__ norms,
                         const float* __restrict__ bias, const void* batch) {
    int node = (blockIdx.x * blockDim.x + threadIdx.x) >> 5;
    if (node >= NN) return;
    int lane = threadIdx.x & 31;
    int q = lane >> 3, p = lane & 7;
    float acc[8] = {};
    agg_core(node, h, rows, norms, q, p, acc);
    if (q == 0) {
        int g = load_idx(batch, node, g_is64_batch);
        float4 b0 = *(const float4*)&bias[8 * p];
        float4 b1 = *(const float4*)&bias[8 * p + 4];
        float4 o0 = make_float4(fmaxf(acc[0] + b0.x, 0.f), fmaxf(acc[1] + b0.y, 0.f),
                                fmaxf(acc[2] + b0.z, 0.f), fmaxf(acc[3] + b0.w, 0.f));
        float4 o1 = make_float4(fmaxf(acc[4] + b1.x, 0.f), fmaxf(acc[5] + b1.y, 0.f),
                                fmaxf(acc[6] + b1.z, 0.f), fmaxf(acc[7] + b1.w, 0.f));
        float* row = g_sums + g * D + 8 * p;
        red_add_v4((float4*)row, o0);
        red_add_v4((float4*)(row + 4), o1);
        if (p == 0) atomicAdd(&g_cnt[g], 1.0f);
    }
}

// ---------------- fused MLP tail: lin1 -> fc0 -> fc1 -> lin2 ----------------
__global__ void tail_kernel(const float* __restrict__ W1, const float* __restrict__ b1,
                            const float* __restrict__ fcw, const float* __restrict__ fcb,
                            const float* __restrict__ w2, const float* __restrict__ b2,
                            float* __restrict__ out) {
    int g = blockIdx.x, tid = threadIdx.x;  // 64 threads
    __shared__ float buf[2][64];
    __shared__ float red[64];

    buf[0][tid] = g_sums[g * D + tid] / fmaxf(g_cnt[g], 1.f);
    __syncthreads();
    {
        float acc = 0.f;
#pragma unroll
        for (int k = 0; k < 64; k++) acc += buf[0][k] * W1[k * D + tid];
        buf[1][tid] = fmaxf(acc + b1[tid], 0.f);
        __syncthreads();
    }
    int cur = 1;
    for (int L = 0; L < 2; L++) {
        const float* W = fcw + L * D * D;
        float acc = 0.f;
#pragma unroll
        for (int k = 0; k < 64; k++) acc += buf[cur][k] * W[k * D + tid];
        __syncthreads();
        buf[cur ^ 1][tid] = fmaxf(acc + fcb[L * D + tid], 0.f);
        cur ^= 1;
        __syncthreads();
    }
    red[tid] = buf[cur][tid] * w2[tid];
    __syncthreads();
    if (tid < 32) {
        float s = red[tid] + red[tid + 32];
#pragma unroll
        for (int off = 16; off; off >>= 1) s += __shfl_down_sync(0xffffffffu, s, off);
        if (tid == 0) out[g] = s + b2[0];
    }
}

// ---------------- launch ----------------
extern "C" void kernel_launch(void* const* d_in, const int* in_sizes, int n_in,
                              void* d_out, int out_size) {
    const float* x      = (const float*)d_in[0];
    const void*  ei     = d_in[1];
    const float* ew     = (const float*)d_in[2];
    const void*  batch  = d_in[3];
    const float* lin0_w = (const float*)d_in[4];
    const float* lin0_b = (const float*)d_in[5];
    const float* conv_w = (const float*)d_in[6];
    const float* conv_b = (const float*)d_in[7];
    const float* lin1_w = (const float*)d_in[8];
    const float* lin1_b = (const float*)d_in[9];
    const float* fc_w   = (const float*)d_in[10];
    const float* fc_b   = (const float*)d_in[11];
    const float* lin2_w = (const float*)d_in[12];
    const float* lin2_b = (const float*)d_in[13];
    float* out = (float*)d_out;

    float *p_out0, *p_aggA, *p_aggB, *p_deg, *p_sums, *p_cnt, *p_norms;
    int *p_cntn, *p_fill, *p_rows;
    uint4* p_h;
    cudaGetSymbolAddress((void**)&p_out0, g_out0);
    cudaGetSymbolAddress((void**)&p_h,    g_hh);
    cudaGetSymbolAddress((void**)&p_aggA, g_aggA);
    cudaGetSymbolAddress((void**)&p_aggB, g_aggB);
    cudaGetSymbolAddress((void**)&p_deg,  g_deg);
    cudaGetSymbolAddress((void**)&p_sums, g_sums);
    cudaGetSymbolAddress((void**)&p_cnt,  g_cnt);
    cudaGetSymbolAddress((void**)&p_cntn, g_cntn);
    cudaGetSymbolAddress((void**)&p_fill, g_fill);
    cudaGetSymbolAddress((void**)&p_rows, g_csr_row);
    cudaGetSymbolAddress((void**)&p_norms, g_csr_norm);

    detect_kernel<<<1, 32>>>((const int*)ei, (const int*)batch);

    cudaMemsetAsync(p_deg, 0, NN * sizeof(float));
    cudaMemsetAsync(p_cntn, 0, NN * sizeof(int));
    cudaMemsetAsync(p_fill, 0, NN * sizeof(int));

    deg_kernel<<<(EE + 255) / 256, 256>>>(ei, ew);
    scan1_kernel<<<SCAN_NB, SCAN_T>>>();
    scan2_kernel<<<1, 256>>>();
    scan3_kernel<<<(NN + 255) / 256, 256>>>();
    scatter_kernel<<<(EE + 255) / 256, 256>>>(ei, ew);

    const int GB = (NN + 127) / 128;
    gemm64<FIN, 20, false><<<GB, 256>>>(x, lin0_w, lin0_b, p_out0, NN);

    cudaMemsetAsync(p_sums, 0, GG * D * sizeof(float));
    cudaMemsetAsync(p_cnt, 0, GG * sizeof(float));

    float* bufs[2] = {p_aggA, p_aggB};
    const float* Ain = p_out0;
    const int AGB = (NN * 32 + 255) / 256;
    for (int i = 0; i < 4; i++) {
        gemm64<D, 32, true><<<GB, 256>>>(Ain, conv_w + i * D * D, nullptr, p_h, NN);
        if (i < 3) {
            float* agg = bufs[i & 1];
            agg_half<<<AGB, 256>>>(p_h, p_rows, p_norms, conv_b + i * D, agg);
            Ain = agg;
        } else {
            agg_pool<<<AGB, 256>>>(p_h, p_rows, p_norms, conv_b + i * D, batch);
        }
    }

    tail_kernel<<<GG, 64>>>(lin1_w, lin1_b, fc_w, fc_b, lin2_w, lin2_b, out);
}